// round 4
// baseline (speedup 1.0000x reference)
#include <cuda_runtime.h>
#include <float.h>
#include <math.h>
#include <stdint.h>

// Problem constants
#define NPTS 12288
#define DIM 64
#define KNN 16
#define EPS 1e-5f
#define DIAG_BIAS 1e6f

// Tiling
#define THREADS 512
#define BI 128
#define BJ 128
#define NSEG 3
#define SEGJ (NPTS / NSEG)        // 4096
#define NTILES (SEGJ / BJ)        // 32
#define NROWBLK (NPTS / BI)       // 96
#define KSTEPS (DIM / 2)          // 32

// smem strides (floats)
#define SI_STRIDE 260             // 128 rows * 2 + 4 pad
#define SJ_STRIDE 260
#define SD_STRIDE 132             // 128 + 4

#define SI_OFF 0
#define SJ_OFF (KSTEPS * SI_STRIDE)              // 8320
#define SJ_BUF (KSTEPS * SJ_STRIDE)              // 8320
#define SD_OFF (SJ_OFF + 2 * SJ_BUF)             // 24960
#define SSQI_OFF (SD_OFF + BI * SD_STRIDE)       // 41856
#define SSQJ_OFF (SSQI_OFF + BI)                 // 41984 (2 x 128)
#define LV_OFF (SSQJ_OFF + 2 * BJ)               // 42240
#define LI_OFF (LV_OFF + THREADS * KNN)          // 50432
#define SMEM_FLOATS (LI_OFF + (THREADS * KNN) / 2) // 54528
#define SMEM_BYTES (SMEM_FLOATS * 4)             // 218112

// Scratch
__device__ float g_sq[NPTS];
__device__ float g_colsum[DIM];
__device__ float g_sigma_inv;
__device__ float g_vals[NPTS * NSEG * KNN];
__device__ int   g_idx [NPTS * NSEG * KNN];

typedef unsigned long long u64;

__device__ __forceinline__ u64 ffma2(u64 a, u64 b, u64 c) {
    u64 d;
    asm("fma.rn.f32x2 %0, %1, %2, %3;" : "=l"(d) : "l"(a), "l"(b), "l"(c));
    return d;
}
__device__ __forceinline__ float pairsum(u64 a) {
    float lo = __uint_as_float((unsigned)(a & 0xffffffffull));
    float hi = __uint_as_float((unsigned)(a >> 32));
    return lo + hi;
}
__device__ __forceinline__ uint32_t sptr(const void* p) {
    return (uint32_t)__cvta_generic_to_shared(p);
}
__device__ __forceinline__ void cp_async8(uint32_t dst, const void* src) {
    asm volatile("cp.async.ca.shared.global [%0], [%1], 8;" :: "r"(dst), "l"(src));
}
__device__ __forceinline__ void cp_async4(uint32_t dst, const void* src) {
    asm volatile("cp.async.ca.shared.global [%0], [%1], 4;" :: "r"(dst), "l"(src));
}
#define CP_COMMIT() asm volatile("cp.async.commit_group;")
#define CP_WAIT0()  asm volatile("cp.async.wait_group 0;")

// chunk swizzle (16B granules): involution, toggles bit0 by bit3
__device__ __forceinline__ int swz(int c) { return c ^ ((c >> 3) & 1); }

// ---------------------------------------------------------------------------
__global__ void sq_kernel(const float* __restrict__ coords) {
    int row = blockIdx.x * 256 + threadIdx.x;
    const float4* p = (const float4*)(coords + (size_t)row * DIM);
    float s = 0.f;
#pragma unroll
    for (int t = 0; t < DIM / 4; ++t) {
        float4 v = p[t];
        s += v.x * v.x + v.y * v.y + v.z * v.z + v.w * v.w;
    }
    g_sq[row] = s;
}

__global__ void colsum_kernel(const float* __restrict__ coords) {
    __shared__ float red[256];
    int d = blockIdx.x;
    float s = 0.f;
    for (int r = threadIdx.x; r < NPTS; r += 256)
        s += coords[(size_t)r * DIM + d];
    red[threadIdx.x] = s;
    __syncthreads();
    for (int off = 128; off > 0; off >>= 1) {
        if (threadIdx.x < off) red[threadIdx.x] += red[threadIdx.x + off];
        __syncthreads();
    }
    if (threadIdx.x == 0) g_colsum[d] = red[0];
}

__global__ void sigma_kernel() {
    __shared__ double red[256];
    double s = 0.0;
    for (int r = threadIdx.x; r < NPTS; r += 256)
        s += (double)g_sq[r];
    red[threadIdx.x] = s;
    __syncthreads();
    for (int off = 128; off > 0; off >>= 1) {
        if (threadIdx.x < off) red[threadIdx.x] += red[threadIdx.x + off];
        __syncthreads();
    }
    if (threadIdx.x == 0) {
        double sumsq = red[0];
        double nrm2 = 0.0;
        for (int d = 0; d < DIM; ++d) {
            double c = (double)g_colsum[d];
            nrm2 += c * c;
        }
        const double Nd = (double)NPTS;
        double total = 2.0 * Nd * sumsq - 2.0 * nrm2
                     + Nd * Nd * (double)EPS + Nd * (double)DIAG_BIAS;
        double sigma2 = total / (Nd * Nd);
        g_sigma_inv = (float)(1.0 / (sigma2 + (double)EPS));
    }
}

// register-array sorted insert (kernel C)
__device__ __forceinline__ void topk_insert(float (&vals)[KNN], int (&idx)[KNN],
                                            float v, int id) {
#pragma unroll
    for (int t = 0; t < KNN; ++t) {
        if (v < vals[t]) {
            float tv = vals[t]; vals[t] = v; v = tv;
            int   ti = idx[t];  idx[t]  = id; id = ti;
        }
    }
}

// smem sorted insert; caller guarantees v < lv[KNN-1] (rare path)
__device__ __forceinline__ void smem_insert(float* __restrict__ lv,
                                            unsigned short* __restrict__ li,
                                            float v, int id, float& thr) {
    int t = KNN - 1;
    while (t > 0) {
        float p = lv[t - 1];
        if (p <= v) break;
        lv[t] = p;
        li[t] = li[t - 1];
        --t;
    }
    lv[t] = v;
    li[t] = (unsigned short)id;
    thr = lv[KNN - 1];
}

// ---------------------------------------------------------------------------
// Kernel B: 128x128 distance tiles, 8x4 per-thread register tile (fp32x2),
// swizzled j-layout (conflict-free LDS), cp.async double-buffered staging,
// streaming top-16 with smem lists + register threshold.
// ---------------------------------------------------------------------------
__device__ __forceinline__ void issue_jtile(const float* __restrict__ coords,
                                            int jbase, float* sjb, float* ssqjb,
                                            int tid) {
#pragma unroll
    for (int u = 0; u < 8; ++u) {
        int e = u * THREADS + tid;       // 0..4095
        int s = e & 31;                  // k-pair
        int r = e >> 5;                  // row 0..127
        const float* src = coords + (size_t)(jbase + r) * DIM + 2 * s;
        int pc = swz(r >> 1);
        float* dst = sjb + s * SJ_STRIDE + pc * 4 + (r & 1) * 2;
        cp_async8(sptr(dst), src);
    }
    if (tid < BJ) cp_async4(sptr(ssqjb + tid), &g_sq[jbase + tid]);
}

__global__ void __launch_bounds__(THREADS, 1)
knn4_kernel(const float* __restrict__ coords) {
    extern __shared__ float smem[];
    float* si   = smem + SI_OFF;
    float* sj   = smem + SJ_OFF;
    float* sd   = smem + SD_OFF;
    float* ssqi = smem + SSQI_OFF;
    float* ssqj = smem + SSQJ_OFF;

    const int tid  = threadIdx.x;
    const int ty   = tid >> 5;        // 0..15 -> rows ty*8..+7
    const int tx   = tid & 31;        // 0..31 -> cols tx*4..+3
    const int row0 = blockIdx.x * BI;
    const int jseg = blockIdx.y * SEGJ;

    // per-thread top-k list in smem, threshold in register
    float*          lv = smem + LV_OFF + tid * KNN;
    unsigned short* li = (unsigned short*)(smem + LI_OFF) + tid * KNN;
    float thr = FLT_MAX;
#pragma unroll
    for (int t = 0; t < KNN; ++t) { lv[t] = FLT_MAX; li[t] = 0; }

    // prologue: stage i-tile (plain layout) + j-tile 0 (swizzled) via cp.async
    {
#pragma unroll
        for (int u = 0; u < 8; ++u) {
            int e = u * THREADS + tid;   // 0..4095
            int s = e & 31;
            int r = e >> 5;
            const float* src = coords + (size_t)(row0 + r) * DIM + 2 * s;
            float* dst = si + s * SI_STRIDE + r * 2;
            cp_async8(sptr(dst), src);
        }
        if (tid < BI) cp_async4(sptr(ssqi + tid), &g_sq[row0 + tid]);
        issue_jtile(coords, jseg, sj, ssqj, tid);
        CP_COMMIT();
    }

    // bj swizzled lane addresses (fixed per thread)
    const int pc0 = swz(2 * tx);
    const int pc1 = swz(2 * tx + 1);

    const int srow  = tid >> 2;   // 0..127
    const int squad = tid & 3;    // 32 cols each

    int buf = 0;
    for (int tile = 0; tile < NTILES; ++tile) {
        const int jbase = jseg + tile * BJ;
        CP_WAIT0();
        __syncthreads();           // sj[buf]+ssqj[buf] ready; sd free

        if (tile + 1 < NTILES) {
            issue_jtile(coords, jbase + BJ, sj + (buf ^ 1) * SJ_BUF,
                        ssqj + (buf ^ 1) * BJ, tid);
            CP_COMMIT();
        }

        // ---- compute 8x4 tile, packed fp32x2 over 32 k-steps ----
        u64 acc[8][4];
#pragma unroll
        for (int r = 0; r < 8; ++r)
#pragma unroll
            for (int c = 0; c < 4; ++c) acc[r][c] = 0ull;

        const float* aib = si + ty * 16;             // rows ty*8 (8 pairs)
        const float* sjb = sj + buf * SJ_BUF;
#pragma unroll 4
        for (int s = 0; s < KSTEPS; ++s) {
            u64 ai[8], bj[4];
            {
                const ulonglong2* p = (const ulonglong2*)(aib + s * SI_STRIDE);
                ulonglong2 a0 = p[0], a1 = p[1], a2 = p[2], a3 = p[3];
                ai[0] = a0.x; ai[1] = a0.y; ai[2] = a1.x; ai[3] = a1.y;
                ai[4] = a2.x; ai[5] = a2.y; ai[6] = a3.x; ai[7] = a3.y;
            }
            {
                const float* sb = sjb + s * SJ_STRIDE;
                ulonglong2 b0 = *(const ulonglong2*)(sb + pc0 * 4);
                ulonglong2 b1 = *(const ulonglong2*)(sb + pc1 * 4);
                bj[0] = b0.x; bj[1] = b0.y; bj[2] = b1.x; bj[3] = b1.y;
            }
#pragma unroll
            for (int r = 0; r < 8; ++r)
#pragma unroll
                for (int c = 0; c < 4; ++c)
                    acc[r][c] = ffma2(ai[r], bj[c], acc[r][c]);
        }

        // ---- epilogue: distances -> sd ----
        {
            float sqj4[4];
#pragma unroll
            for (int c = 0; c < 4; ++c) sqj4[c] = ssqj[buf * BJ + tx * 4 + c];
#pragma unroll
            for (int r = 0; r < 8; ++r) {
                const int lr = ty * 8 + r;
                const int gr = row0 + lr;
                const float base = ssqi[lr] + EPS;
                float4 dv;
                float* dd = (float*)&dv;
#pragma unroll
                for (int c = 0; c < 4; ++c) {
                    float dot = pairsum(acc[r][c]);
                    float d = fmaf(-2.f, dot, base + sqj4[c]);
                    if (gr == jbase + tx * 4 + c) d += DIAG_BIAS;
                    dd[c] = d;
                }
                *(float4*)(sd + lr * SD_STRIDE + tx * 4) = dv;
            }
        }
        __syncthreads();

        // ---- streaming top-16: 4 threads per row, 32 cols each ----
        {
            const float* rp = sd + srow * SD_STRIDE + squad * 32;
            const int cbase = jbase + squad * 32;
#pragma unroll
            for (int c4 = 0; c4 < 8; ++c4) {
                float4 d = *(const float4*)(rp + c4 * 4);
                const int cb = cbase + c4 * 4;
                if (d.x < thr) smem_insert(lv, li, d.x, cb + 0, thr);
                if (d.y < thr) smem_insert(lv, li, d.y, cb + 1, thr);
                if (d.z < thr) smem_insert(lv, li, d.z, cb + 2, thr);
                if (d.w < thr) smem_insert(lv, li, d.w, cb + 3, thr);
            }
        }
        buf ^= 1;
    }

    // ---- merge the 4 squad lists per row, emit candidates ----
    __syncthreads();
    if (squad == 0) {
#pragma unroll
        for (int p = 1; p < 4; ++p) {
            const float*          pv = lv + p * KNN;
            const unsigned short* pi = li + p * KNN;
#pragma unroll
            for (int t = 0; t < KNN; ++t) {
                float c = pv[t];
                if (c < thr) smem_insert(lv, li, c, (int)pi[t], thr);
            }
        }
        const size_t o = ((size_t)(row0 + srow) * NSEG + blockIdx.y) * KNN;
#pragma unroll
        for (int t = 0; t < KNN; ++t) {
            g_vals[o + t] = lv[t];
            g_idx [o + t] = (int)li[t];
        }
    }
}

// ---------------------------------------------------------------------------
// Kernel C: merge NSEG candidate lists per row, compute Laplacian.
// ---------------------------------------------------------------------------
__global__ void merge_lap_kernel(const float* __restrict__ potential,
                                 float* __restrict__ out) {
    const int row = blockIdx.x * 256 + threadIdx.x;

    float vals[KNN];
    int   idx[KNN];
#pragma unroll
    for (int t = 0; t < KNN; ++t) { vals[t] = FLT_MAX; idx[t] = 0; }

    const size_t base = (size_t)row * NSEG * KNN;
    for (int s = 0; s < NSEG; ++s) {
#pragma unroll
        for (int kk = 0; kk < KNN; ++kk) {
            float c = g_vals[base + s * KNN + kk];
            if (c < vals[KNN - 1]) topk_insert(vals, idx, c, g_idx[base + s * KNN + kk]);
        }
    }

    const float inv = g_sigma_inv;
    const float vi  = potential[row];
    float lap = 0.f;
#pragma unroll
    for (int t = 0; t < KNN; ++t) {
        float w = expf(-vals[t] * inv);
        lap += w * (potential[idx[t]] - vi);
    }
    out[row] = lap;
}

// ---------------------------------------------------------------------------
extern "C" void kernel_launch(void* const* d_in, const int* in_sizes, int n_in,
                              void* d_out, int out_size) {
    const float* coords    = (const float*)d_in[0];
    const float* potential = (const float*)d_in[1];
    float* out = (float*)d_out;

    cudaFuncSetAttribute(knn4_kernel,
                         cudaFuncAttributeMaxDynamicSharedMemorySize,
                         SMEM_BYTES);

    sq_kernel<<<NPTS / 256, 256>>>(coords);
    colsum_kernel<<<DIM, 256>>>(coords);
    sigma_kernel<<<1, 256>>>();

    dim3 grid(NROWBLK, NSEG);
    knn4_kernel<<<grid, THREADS, SMEM_BYTES>>>(coords);

    merge_lap_kernel<<<NPTS / 256, 256>>>(potential, out);
}